// round 13
// baseline (speedup 1.0000x reference)
#include <cuda_runtime.h>
#include <cstdint>

// Problem constants: G=512, GP=256, keys fit in 24 bits since b==0.
#define NKEYS  (1u << 24)          // 16,777,216 possible parent keys
#define NWORDS (1u << 19)          // bitmap words (32 keys/word)
#define NBLKS  (NWORDS / 1024)     // 512 scan blocks
#define NMAX   4000000

// Scratch (static device globals)
__device__ unsigned g_bitmap[NWORDS];
__device__ unsigned g_wprefix[NWORDS];    // per-word excl popcount prefix (within 1024-word block)
__device__ unsigned g_blocksums[NBLKS];   // 1024-word-block exclusive prefix
__device__ unsigned g_total;              // number of unique keys
__device__ unsigned g_done;               // last-block-done counter (reset each run)
__device__ unsigned g_combined[NMAX];     // (key<<3)|offset per point

__global__ void k_zero_bitmap() {
    unsigned i = blockIdx.x * blockDim.x + threadIdx.x;
    if (i < NWORDS / 4) reinterpret_cast<uint4*>(g_bitmap)[i] = make_uint4(0, 0, 0, 0);
}

// ---------------------------------------------------------------------------
// Pass 1: per point, compute key + child-offset, mark presence bit.
// ---------------------------------------------------------------------------
__global__ void k_build(const int4* __restrict__ coords, int n) {
    int i = blockIdx.x * blockDim.x + threadIdx.x;
    if (i >= n) return;
    int4 c = coords[i];
    unsigned key = (((unsigned)c.x * 256u + (((unsigned)c.y) >> 1)) * 256u
                    + (((unsigned)c.z) >> 1)) * 256u + (((unsigned)c.w) >> 1);
    unsigned off = (((unsigned)c.y & 1u) << 2) | (((unsigned)c.z & 1u) << 1)
                 | ((unsigned)c.w & 1u);
    g_combined[i] = (key << 3) | off;
    atomicOr(&g_bitmap[key >> 5], 1u << (key & 31u));
}

// ---------------------------------------------------------------------------
// Pass 2 (fused): per-1024-word-block exclusive scan of bitmap popcounts;
// the LAST block to finish also scans the 512 block totals and publishes
// g_total (then resets g_done for the next graph replay).
// ---------------------------------------------------------------------------
__global__ __launch_bounds__(1024) void k_scan_words() {
    __shared__ unsigned warp_sums[32];
    __shared__ int is_last;
    unsigned w = blockIdx.x * 1024u + threadIdx.x;
    unsigned c = __popc(g_bitmap[w]);
    unsigned v = c;
    #pragma unroll
    for (int d = 1; d < 32; d <<= 1) {
        unsigned t = __shfl_up_sync(0xFFFFFFFFu, v, d);
        if ((threadIdx.x & 31u) >= (unsigned)d) v += t;
    }
    if ((threadIdx.x & 31u) == 31u) warp_sums[threadIdx.x >> 5] = v;
    __syncthreads();
    if (threadIdx.x < 32) {
        unsigned s = warp_sums[threadIdx.x];
        #pragma unroll
        for (int d = 1; d < 32; d <<= 1) {
            unsigned t = __shfl_up_sync(0xFFFFFFFFu, s, d);
            if (threadIdx.x >= (unsigned)d) s += t;
        }
        warp_sums[threadIdx.x] = s;
    }
    __syncthreads();
    unsigned warp_off = (threadIdx.x >= 32) ? warp_sums[(threadIdx.x >> 5) - 1] : 0u;
    g_wprefix[w] = warp_off + v - c;
    if (threadIdx.x == 1023) g_blocksums[blockIdx.x] = warp_off + v;

    // -- last-block-done: fold the 512-entry block-total scan in here --
    __threadfence();
    __syncthreads();
    if (threadIdx.x == 0) is_last = (atomicAdd(&g_done, 1u) == gridDim.x - 1u);
    __syncthreads();
    if (!is_last) return;

    unsigned bc = (threadIdx.x < NBLKS) ? g_blocksums[threadIdx.x] : 0u;
    unsigned bv = bc;
    #pragma unroll
    for (int d = 1; d < 32; d <<= 1) {
        unsigned t = __shfl_up_sync(0xFFFFFFFFu, bv, d);
        if ((threadIdx.x & 31u) >= (unsigned)d) bv += t;
    }
    if ((threadIdx.x & 31u) == 31u) warp_sums[threadIdx.x >> 5] = bv;
    __syncthreads();
    if (threadIdx.x < 32) {
        unsigned s = warp_sums[threadIdx.x];
        #pragma unroll
        for (int d = 1; d < 32; d <<= 1) {
            unsigned t = __shfl_up_sync(0xFFFFFFFFu, s, d);
            if (threadIdx.x >= (unsigned)d) s += t;
        }
        warp_sums[threadIdx.x] = s;
    }
    __syncthreads();
    unsigned boff = (threadIdx.x >= 32) ? warp_sums[(threadIdx.x >> 5) - 1] : 0u;
    if (threadIdx.x < NBLKS) g_blocksums[threadIdx.x] = boff + bv - bc;
    if (threadIdx.x == NBLKS - 1) g_total = boff + bv;
    __syncthreads();
    if (threadIdx.x == 0) g_done = 0;   // reset for next graph replay
}

// ---------------------------------------------------------------------------
// Pass 3 (per key half): WORD-per-thread emit. Each thread owns one bitmap
// word: iterate set bits, write coords row (float32) + zero the feats row at
// consecutive ranks. Warms L2 with exactly the lines the scatter will RMW.
// ---------------------------------------------------------------------------
__global__ void k_emit_half(float4* __restrict__ out_coords,
                            float4* __restrict__ out_feats4, unsigned wordbase) {
    unsigned w = wordbase + blockIdx.x * blockDim.x + threadIdx.x;
    unsigned word = g_bitmap[w];
    if (!word) return;
    unsigned rank = g_wprefix[w] + g_blocksums[w >> 10];
    unsigned kb = w << 5;
    const float4 z = make_float4(0.f, 0.f, 0.f, 0.f);
    while (word) {
        unsigned bit = (unsigned)__ffs(word) - 1u;
        word &= word - 1u;
        unsigned k = kb + bit;
        out_coords[rank] = make_float4((float)(k >> 24), (float)((k >> 16) & 255u),
                                       (float)((k >> 8) & 255u), (float)(k & 255u));
        out_feats4[(size_t)rank * 2]     = z;
        out_feats4[(size_t)rank * 2 + 1] = z;
        rank++;
    }
}

// ---------------------------------------------------------------------------
// Pass 4 (per key half): predicated scatter; atomics hit the ~57MB
// just-zeroed half -> mostly L2-resident RMW.
// ---------------------------------------------------------------------------
__global__ void k_scatter_half(const float* __restrict__ feats,
                               float* __restrict__ out_feats, int n, unsigned half) {
    int i = blockIdx.x * blockDim.x + threadIdx.x;
    if (i >= n) return;
    unsigned comb = g_combined[i];
    unsigned key  = comb >> 3;
    if ((key >> 23) != half) return;
    unsigned off  = comb & 7u;
    unsigned w    = key >> 5;
    unsigned bit  = key & 31u;
    unsigned word = g_bitmap[w];
    unsigned rank = g_wprefix[w] + g_blocksums[w >> 10]
                  + (unsigned)__popc(word & ((1u << bit) - 1u));
    atomicAdd(&out_feats[(size_t)rank * 8u + off], feats[i]);
}

// ---------------------------------------------------------------------------
// Pass 5: invalid tail rows (rank >= g_total): coords=-1, feats=0.
// ---------------------------------------------------------------------------
__global__ void k_fill_invalid(float4* __restrict__ out_coords,
                               float4* __restrict__ out_feats4, int n) {
    int i = blockIdx.x * blockDim.x + threadIdx.x;
    if (i >= n || (unsigned)i < g_total) return;
    out_coords[i] = make_float4(-1.f, -1.f, -1.f, -1.f);
    out_feats4[(size_t)i * 2]     = make_float4(0.f, 0.f, 0.f, 0.f);
    out_feats4[(size_t)i * 2 + 1] = make_float4(0.f, 0.f, 0.f, 0.f);
}

extern "C" void kernel_launch(void* const* d_in, const int* in_sizes, int n_in,
                              void* d_out, int out_size) {
    const int4*  coords = (const int4*)d_in[0];
    const float* feats  = (const float*)d_in[1];
    int n = in_sizes[0] / 4;   // N points

    float4* out_coords = (float4*)d_out;
    float*  out_feats  = (float*)((char*)d_out + (size_t)n * 4 * sizeof(float));
    float4* out_feats4 = (float4*)out_feats;

    k_zero_bitmap <<<((NWORDS / 4) + 255) / 256, 256>>>();
    k_build       <<<(n + 255) / 256, 256>>>(coords, n);
    k_scan_words  <<<NBLKS, 1024>>>();     // fused: also scans block totals
    k_fill_invalid<<<(n + 255) / 256, 256>>>(out_coords, out_feats4, n);
    // Half 0: emit (zero+coords, warm L2), then scatter into it.
    k_emit_half   <<<(NWORDS / 2) / 256, 256>>>(out_coords, out_feats4, 0u);
    k_scatter_half<<<(n + 255) / 256, 256>>>(feats, out_feats, n, 0u);
    // Half 1.
    k_emit_half   <<<(NWORDS / 2) / 256, 256>>>(out_coords, out_feats4, NWORDS / 2);
    k_scatter_half<<<(n + 255) / 256, 256>>>(feats, out_feats, n, 1u);
}

// round 14
// speedup vs baseline: 1.2510x; 1.2510x over previous
#include <cuda_runtime.h>
#include <cstdint>

// Problem constants: G=512, GP=256, keys fit in 24 bits since b==0.
#define NKEYS  (1u << 24)          // 16,777,216 possible parent keys
#define NWORDS (1u << 19)          // bitmap words (32 keys/word)
#define NBLKS  (NWORDS / 1024)     // 512 scan blocks
#define NMAX   4000000

// Scratch (static device globals)
__device__ unsigned g_bitmap[NWORDS];
__device__ unsigned g_wprefix[NWORDS];    // per-word excl popcount prefix (within 1024-word block)
__device__ unsigned g_blocksums[NBLKS];   // 1024-word-block exclusive prefix
__device__ unsigned g_total;              // number of unique keys
__device__ unsigned g_done;               // last-block-done counter (reset each run)
__device__ unsigned g_combined[NMAX];     // (key<<3)|offset per point

__global__ void k_zero_bitmap() {
    unsigned i = blockIdx.x * blockDim.x + threadIdx.x;
    if (i < NWORDS / 4) reinterpret_cast<uint4*>(g_bitmap)[i] = make_uint4(0, 0, 0, 0);
}

// ---------------------------------------------------------------------------
// Pass 1: per point, compute key + child-offset, mark presence bit.
// ---------------------------------------------------------------------------
__global__ void k_build(const int4* __restrict__ coords, int n) {
    int i = blockIdx.x * blockDim.x + threadIdx.x;
    if (i >= n) return;
    int4 c = coords[i];
    unsigned key = (((unsigned)c.x * 256u + (((unsigned)c.y) >> 1)) * 256u
                    + (((unsigned)c.z) >> 1)) * 256u + (((unsigned)c.w) >> 1);
    unsigned off = (((unsigned)c.y & 1u) << 2) | (((unsigned)c.z & 1u) << 1)
                 | ((unsigned)c.w & 1u);
    g_combined[i] = (key << 3) | off;
    atomicOr(&g_bitmap[key >> 5], 1u << (key & 31u));
}

// ---------------------------------------------------------------------------
// Pass 2 (fused): per-1024-word-block exclusive scan of bitmap popcounts;
// the LAST block to finish also scans the 512 block totals and publishes
// g_total (then resets g_done for the next graph replay).
// ---------------------------------------------------------------------------
__global__ __launch_bounds__(1024) void k_scan_words() {
    __shared__ unsigned warp_sums[32];
    __shared__ int is_last;
    unsigned w = blockIdx.x * 1024u + threadIdx.x;
    unsigned c = __popc(g_bitmap[w]);
    unsigned v = c;
    #pragma unroll
    for (int d = 1; d < 32; d <<= 1) {
        unsigned t = __shfl_up_sync(0xFFFFFFFFu, v, d);
        if ((threadIdx.x & 31u) >= (unsigned)d) v += t;
    }
    if ((threadIdx.x & 31u) == 31u) warp_sums[threadIdx.x >> 5] = v;
    __syncthreads();
    if (threadIdx.x < 32) {
        unsigned s = warp_sums[threadIdx.x];
        #pragma unroll
        for (int d = 1; d < 32; d <<= 1) {
            unsigned t = __shfl_up_sync(0xFFFFFFFFu, s, d);
            if (threadIdx.x >= (unsigned)d) s += t;
        }
        warp_sums[threadIdx.x] = s;
    }
    __syncthreads();
    unsigned warp_off = (threadIdx.x >= 32) ? warp_sums[(threadIdx.x >> 5) - 1] : 0u;
    g_wprefix[w] = warp_off + v - c;
    if (threadIdx.x == 1023) g_blocksums[blockIdx.x] = warp_off + v;

    // -- last-block-done: fold the 512-entry block-total scan in here --
    __threadfence();
    __syncthreads();
    if (threadIdx.x == 0) is_last = (atomicAdd(&g_done, 1u) == gridDim.x - 1u);
    __syncthreads();
    if (!is_last) return;

    unsigned bc = (threadIdx.x < NBLKS) ? g_blocksums[threadIdx.x] : 0u;
    unsigned bv = bc;
    #pragma unroll
    for (int d = 1; d < 32; d <<= 1) {
        unsigned t = __shfl_up_sync(0xFFFFFFFFu, bv, d);
        if ((threadIdx.x & 31u) >= (unsigned)d) bv += t;
    }
    if ((threadIdx.x & 31u) == 31u) warp_sums[threadIdx.x >> 5] = bv;
    __syncthreads();
    if (threadIdx.x < 32) {
        unsigned s = warp_sums[threadIdx.x];
        #pragma unroll
        for (int d = 1; d < 32; d <<= 1) {
            unsigned t = __shfl_up_sync(0xFFFFFFFFu, s, d);
            if (threadIdx.x >= (unsigned)d) s += t;
        }
        warp_sums[threadIdx.x] = s;
    }
    __syncthreads();
    unsigned boff = (threadIdx.x >= 32) ? warp_sums[(threadIdx.x >> 5) - 1] : 0u;
    if (threadIdx.x < NBLKS) g_blocksums[threadIdx.x] = boff + bv - bc;
    if (threadIdx.x == NBLKS - 1) g_total = boff + bv;
    __syncthreads();
    if (threadIdx.x == 0) g_done = 0;   // reset for next graph replay
}

// ---------------------------------------------------------------------------
// Pass 3 (per key half): KEY-per-thread emit (coalesced: adjacent active
// lanes write adjacent ranks). Emit sorted unique coords (float32) AND zero
// the row's feats — warms L2 with exactly the lines the scatter will RMW.
// ---------------------------------------------------------------------------
__global__ void k_coords_half(float4* __restrict__ out_coords,
                              float4* __restrict__ out_feats4, unsigned keybase) {
    unsigned k = keybase + blockIdx.x * blockDim.x + threadIdx.x;
    unsigned w    = k >> 5;
    unsigned bit  = k & 31u;
    unsigned word = g_bitmap[w];
    if (!((word >> bit) & 1u)) return;
    unsigned rank = g_wprefix[w] + g_blocksums[w >> 10]
                  + (unsigned)__popc(word & ((1u << bit) - 1u));
    out_coords[rank] = make_float4((float)(k >> 24), (float)((k >> 16) & 255u),
                                   (float)((k >> 8) & 255u), (float)(k & 255u));
    out_feats4[(size_t)rank * 2]     = make_float4(0.f, 0.f, 0.f, 0.f);
    out_feats4[(size_t)rank * 2 + 1] = make_float4(0.f, 0.f, 0.f, 0.f);
}

// ---------------------------------------------------------------------------
// Pass 4 (per key half): predicated scatter; atomics hit the ~57MB
// just-zeroed half -> mostly L2-resident RMW.
// ---------------------------------------------------------------------------
__global__ void k_scatter_half(const float* __restrict__ feats,
                               float* __restrict__ out_feats, int n, unsigned half) {
    int i = blockIdx.x * blockDim.x + threadIdx.x;
    if (i >= n) return;
    unsigned comb = g_combined[i];
    unsigned key  = comb >> 3;
    if ((key >> 23) != half) return;
    unsigned off  = comb & 7u;
    unsigned w    = key >> 5;
    unsigned bit  = key & 31u;
    unsigned word = g_bitmap[w];
    unsigned rank = g_wprefix[w] + g_blocksums[w >> 10]
                  + (unsigned)__popc(word & ((1u << bit) - 1u));
    atomicAdd(&out_feats[(size_t)rank * 8u + off], feats[i]);
}

// ---------------------------------------------------------------------------
// Pass 5: invalid tail rows (rank >= g_total): coords=-1, feats=0.
// Grid-stride starting AT g_total — only tail threads are spawned-equivalent.
// ---------------------------------------------------------------------------
__global__ void k_fill_invalid(float4* __restrict__ out_coords,
                               float4* __restrict__ out_feats4, int n) {
    const float4 z  = make_float4(0.f, 0.f, 0.f, 0.f);
    const float4 m1 = make_float4(-1.f, -1.f, -1.f, -1.f);
    unsigned start = g_total;
    for (unsigned i = start + blockIdx.x * blockDim.x + threadIdx.x; i < (unsigned)n;
         i += gridDim.x * blockDim.x) {
        out_coords[i] = m1;
        out_feats4[(size_t)i * 2]     = z;
        out_feats4[(size_t)i * 2 + 1] = z;
    }
}

extern "C" void kernel_launch(void* const* d_in, const int* in_sizes, int n_in,
                              void* d_out, int out_size) {
    const int4*  coords = (const int4*)d_in[0];
    const float* feats  = (const float*)d_in[1];
    int n = in_sizes[0] / 4;   // N points

    float4* out_coords = (float4*)d_out;
    float*  out_feats  = (float*)((char*)d_out + (size_t)n * 4 * sizeof(float));
    float4* out_feats4 = (float4*)out_feats;

    k_zero_bitmap <<<((NWORDS / 4) + 255) / 256, 256>>>();
    k_build       <<<(n + 255) / 256, 256>>>(coords, n);
    k_scan_words  <<<NBLKS, 1024>>>();     // fused: also scans block totals
    // Half 0: emit (zero+coords, warm L2), then scatter into it.
    k_coords_half <<<(NKEYS / 2) / 256, 256>>>(out_coords, out_feats4, 0u);
    k_scatter_half<<<(n + 255) / 256, 256>>>(feats, out_feats, n, 0u);
    // Half 1.
    k_coords_half <<<(NKEYS / 2) / 256, 256>>>(out_coords, out_feats4, 1u << 23);
    k_scatter_half<<<(n + 255) / 256, 256>>>(feats, out_feats, n, 1u);
    k_fill_invalid<<<960, 256>>>(out_coords, out_feats4, n);
}